// round 14
// baseline (speedup 1.0000x reference)
#include <cuda_runtime.h>
#include <cstdint>

#define NMAX 200000
#define KOFF 27
#define TILE 128
#define TILESMAX ((NMAX + TILE - 1) / TILE)
#define SEGW (TILESMAX + 1)
#define BN_EPS 1e-3f

// ---------------- scratch (__device__ globals; no allocs allowed) ----------
__device__ __align__(256) float g_acc1[(size_t)NMAX * 32];
__device__ __align__(256) float g_x1  [(size_t)NMAX * 32];
__device__ __align__(256) float g_acc2[(size_t)NMAX * 32];
__device__ int   g_seg[KOFF * SEGW];
// [0:64) L1 sum/sumsq  [64:128) L2 sum/sumsq  [128:192) L1 sc/sh  [192:256) L2 sc/sh
__device__ __align__(16) float g_sums[256];

__device__ __forceinline__ unsigned smem_u32(const void* p) {
    return (unsigned)__cvta_generic_to_shared(p);
}
__device__ __forceinline__ void cp_async16(unsigned dst, const void* src) {
    asm volatile("cp.async.cg.shared.global [%0], [%1], 16;\n" :: "r"(dst), "l"(src));
}
#define CP_COMMIT asm volatile("cp.async.commit_group;\n" ::: "memory")
#define CP_WAIT0  asm volatile("cp.async.wait_group 0;\n" ::: "memory")

// ---------------- seg: per (k, dst-tile) pair-range via binary search ------
__global__ void seg_k(const int* __restrict__ rout, int n, int tiles) {
    if (blockIdx.x == 0 && threadIdx.x < 128) g_sums[threadIdx.x] = 0.f;
    int idx = blockIdx.x * blockDim.x + threadIdx.x;
    int total = KOFF * (tiles + 1);
    if (idx >= total) return;
    int k = idx / (tiles + 1), t = idx % (tiles + 1);
    int target = t * TILE;
    if (target > n) target = n;
    const int* a = rout + (size_t)k * n;
    int lo = 0, hi = n;
    while (lo < hi) {
        int mid = (lo + hi) >> 1;
        if (a[mid] < target) lo = mid + 1; else hi = mid;
    }
    g_seg[k * SEGW + t] = lo;
}

// ==================== conv1: pipelined (R4 kernel, verbatim) ===============
template <int CIN, bool BNIN>
__global__ void __launch_bounds__(256) conv_k(
    const float* __restrict__ X, const float* __restrict__ W,
    const int* __restrict__ rin, const int* __restrict__ rout,
    float* __restrict__ out, int n, int statoff)
{
    const int AS  = CIN + 4;
    const int CH  = CIN / 4;
    const int CSH = (CIN == 32) ? 3 : 2;
    const int PF  = CH / 2;
    const int WF4 = CIN * 8;

    extern __shared__ float smem[];
    float* C    = smem;                            // 128*36
    float* AshB = C + 128 * 36;                    // 2 * 128*AS
    float* WshB = AshB + 2 * 128 * AS;             // 2 * CIN*32
    float* red  = WshB + 2 * CIN * 32;             // 512
    float* bns  = red + 512;                       // 64
    int*   dshB = (int*)(bns + 64);                // 2 * 128
    int*   klist = dshB + 256;
    int*   klo   = klist + KOFF;
    int*   kln   = klo + KOFF;
    int*   sst   = kln + KOFF;
    int*   sen   = sst + KOFF;
    int*   nk_sh = sen + KOFF;

    int tx = threadIdx.x;
    int tile = blockIdx.x;
    int r0 = tile * TILE;

    if (BNIN && tx < 64) bns[tx] = g_sums[128 + tx];
    if (tx < KOFF) { sst[tx] = g_seg[tx * SEGW + tile]; sen[tx] = g_seg[tx * SEGW + tile + 1]; }
    for (int i = tx; i < 128 * 36; i += 256) C[i] = 0.f;
    __syncthreads();
    if (tx == 0) {
        int m = 0;
        for (int k = 0; k < KOFF; k++) {
            int L = sen[k] - sst[k];
            if (L > 0) { klist[m] = k; klo[m] = sst[k]; kln[m] = L; m++; }
        }
        *nk_sh = m;
    }
    __syncthreads();
    int nk = *nk_sh;

    float4 pv[PF];
    float4 pw = make_float4(0.f, 0.f, 0.f, 0.f);
    int pdst = 0;
    int curL = 0;

    auto prefetch = [&](int j) {
        int k = klist[j], s = klo[j], L = kln[j];
        curL = L;
        const float4* Wk4 = (const float4*)(W + (size_t)k * CIN * 32);
        if (tx < WF4) pw = Wk4[tx];
        if (tx < L) pdst = __ldg(rout + (size_t)k * n + s + tx);
        #pragma unroll
        for (int i = 0; i < PF; i++) {
            int gi = tx + i * 256;
            int row = gi >> CSH, co = gi & (CH - 1);
            if (row < L) {
                int src = __ldg(rin + (size_t)k * n + s + row);
                float4 v = ((const float4*)(X + (size_t)src * CIN))[co];
                if (BNIN) {
                    float4 sc = *(const float4*)&bns[co * 4];
                    float4 sh = *(const float4*)&bns[32 + co * 4];
                    v.x = fmaxf(fmaf(v.x, sc.x, sh.x), 0.f);
                    v.y = fmaxf(fmaf(v.y, sc.y, sh.y), 0.f);
                    v.z = fmaxf(fmaf(v.z, sc.z, sh.z), 0.f);
                    v.w = fmaxf(fmaf(v.w, sc.w, sh.w), 0.f);
                }
                pv[i] = v;
            }
        }
    };

    if (nk > 0) prefetch(0);

    const int rg = tx >> 3, cg = tx & 7;
    const int rb = rg * 4;

    for (int idx = 0; idx < nk; idx++) {
        int buf = idx & 1;
        int L = curL;
        float* Ash = AshB + buf * 128 * AS;
        float* Wsh = WshB + buf * CIN * 32;
        int*   dsh = dshB + buf * 128;

        if (tx < WF4) ((float4*)Wsh)[tx] = pw;
        if (tx < L) dsh[tx] = pdst - r0;
        #pragma unroll
        for (int i = 0; i < PF; i++) {
            int gi = tx + i * 256;
            int row = gi >> CSH, co = gi & (CH - 1);
            if (row < L) *(float4*)&Ash[row * AS + co * 4] = pv[i];
        }
        __syncthreads();

        if (idx + 1 < nk) prefetch(idx + 1);

        if (rb < L) {
            float4 cc[4];
            #pragma unroll
            for (int i = 0; i < 4; i++) cc[i] = make_float4(0.f, 0.f, 0.f, 0.f);

            #pragma unroll
            for (int c4 = 0; c4 < CIN / 4; c4++) {
                int ci = c4 * 4;
                float4 a0 = *(const float4*)&Ash[(rb + 0) * AS + ci];
                float4 a1 = *(const float4*)&Ash[(rb + 1) * AS + ci];
                float4 a2 = *(const float4*)&Ash[(rb + 2) * AS + ci];
                float4 a3 = *(const float4*)&Ash[(rb + 3) * AS + ci];
                float4 w0 = *(const float4*)&Wsh[(ci + 0) * 32 + cg * 4];
                float4 w1 = *(const float4*)&Wsh[(ci + 1) * 32 + cg * 4];
                float4 w2 = *(const float4*)&Wsh[(ci + 2) * 32 + cg * 4];
                float4 w3 = *(const float4*)&Wsh[(ci + 3) * 32 + cg * 4];

                cc[0].x = fmaf(a0.x, w0.x, cc[0].x); cc[0].y = fmaf(a0.x, w0.y, cc[0].y);
                cc[0].z = fmaf(a0.x, w0.z, cc[0].z); cc[0].w = fmaf(a0.x, w0.w, cc[0].w);
                cc[1].x = fmaf(a1.x, w0.x, cc[1].x); cc[1].y = fmaf(a1.x, w0.y, cc[1].y);
                cc[1].z = fmaf(a1.x, w0.z, cc[1].z); cc[1].w = fmaf(a1.x, w0.w, cc[1].w);
                cc[2].x = fmaf(a2.x, w0.x, cc[2].x); cc[2].y = fmaf(a2.x, w0.y, cc[2].y);
                cc[2].z = fmaf(a2.x, w0.z, cc[2].z); cc[2].w = fmaf(a2.x, w0.w, cc[2].w);
                cc[3].x = fmaf(a3.x, w0.x, cc[3].x); cc[3].y = fmaf(a3.x, w0.y, cc[3].y);
                cc[3].z = fmaf(a3.x, w0.z, cc[3].z); cc[3].w = fmaf(a3.x, w0.w, cc[3].w);

                cc[0].x = fmaf(a0.y, w1.x, cc[0].x); cc[0].y = fmaf(a0.y, w1.y, cc[0].y);
                cc[0].z = fmaf(a0.y, w1.z, cc[0].z); cc[0].w = fmaf(a0.y, w1.w, cc[0].w);
                cc[1].x = fmaf(a1.y, w1.x, cc[1].x); cc[1].y = fmaf(a1.y, w1.y, cc[1].y);
                cc[1].z = fmaf(a1.y, w1.z, cc[1].z); cc[1].w = fmaf(a1.y, w1.w, cc[1].w);
                cc[2].x = fmaf(a2.y, w1.x, cc[2].x); cc[2].y = fmaf(a2.y, w1.y, cc[2].y);
                cc[2].z = fmaf(a2.y, w1.z, cc[2].z); cc[2].w = fmaf(a2.y, w1.w, cc[2].w);
                cc[3].x = fmaf(a3.y, w1.x, cc[3].x); cc[3].y = fmaf(a3.y, w1.y, cc[3].y);
                cc[3].z = fmaf(a3.y, w1.z, cc[3].z); cc[3].w = fmaf(a3.y, w1.w, cc[3].w);

                cc[0].x = fmaf(a0.z, w2.x, cc[0].x); cc[0].y = fmaf(a0.z, w2.y, cc[0].y);
                cc[0].z = fmaf(a0.z, w2.z, cc[0].z); cc[0].w = fmaf(a0.z, w2.w, cc[0].w);
                cc[1].x = fmaf(a1.z, w2.x, cc[1].x); cc[1].y = fmaf(a1.z, w2.y, cc[1].y);
                cc[1].z = fmaf(a1.z, w2.z, cc[1].z); cc[1].w = fmaf(a1.z, w2.w, cc[1].w);
                cc[2].x = fmaf(a2.z, w2.x, cc[2].x); cc[2].y = fmaf(a2.z, w2.y, cc[2].y);
                cc[2].z = fmaf(a2.z, w2.z, cc[2].z); cc[2].w = fmaf(a2.z, w2.w, cc[2].w);
                cc[3].x = fmaf(a3.z, w2.x, cc[3].x); cc[3].y = fmaf(a3.z, w2.y, cc[3].y);
                cc[3].z = fmaf(a3.z, w2.z, cc[3].z); cc[3].w = fmaf(a3.z, w2.w, cc[3].w);

                cc[0].x = fmaf(a0.w, w3.x, cc[0].x); cc[0].y = fmaf(a0.w, w3.y, cc[0].y);
                cc[0].z = fmaf(a0.w, w3.z, cc[0].z); cc[0].w = fmaf(a0.w, w3.w, cc[0].w);
                cc[1].x = fmaf(a1.w, w3.x, cc[1].x); cc[1].y = fmaf(a1.w, w3.y, cc[1].y);
                cc[1].z = fmaf(a1.w, w3.z, cc[1].z); cc[1].w = fmaf(a1.w, w3.w, cc[1].w);
                cc[2].x = fmaf(a2.w, w3.x, cc[2].x); cc[2].y = fmaf(a2.w, w3.y, cc[2].y);
                cc[2].z = fmaf(a2.w, w3.z, cc[2].z); cc[2].w = fmaf(a2.w, w3.w, cc[2].w);
                cc[3].x = fmaf(a3.w, w3.x, cc[3].x); cc[3].y = fmaf(a3.w, w3.y, cc[3].y);
                cc[3].z = fmaf(a3.w, w3.z, cc[3].z); cc[3].w = fmaf(a3.w, w3.w, cc[3].w);
            }

            #pragma unroll
            for (int i = 0; i < 4; i++) {
                int row = rb + i;
                if (row < L) {
                    float* p = &C[dsh[row] * 36 + cg * 4];
                    float4 cv = *(float4*)p;
                    cv.x += cc[i].x; cv.y += cc[i].y;
                    cv.z += cc[i].z; cv.w += cc[i].w;
                    *(float4*)p = cv;
                }
            }
        }
    }
    __syncthreads();

    int nrows = n - r0; if (nrows > 128) nrows = 128;
    for (int i = tx; i < nrows * 8; i += 256) {
        int row = i >> 3, co = i & 7;
        ((float4*)(out + (size_t)(r0 + row) * 32))[co] = *(float4*)&C[row * 36 + co * 4];
    }
    int ch = tx & 31, rb2 = tx >> 5;
    float s = 0.f, q = 0.f;
    for (int r = rb2; r < nrows; r += 8) {
        float v = C[r * 36 + ch];
        s += v;
        q = fmaf(v, v, q);
    }
    red[tx] = s; red[256 + tx] = q;
    __syncthreads();
    if (tx < 32) {
        float S = 0.f, Q = 0.f;
        #pragma unroll
        for (int w = 0; w < 8; w++) { S += red[w * 32 + tx]; Q += red[256 + w * 32 + tx]; }
        atomicAdd(&g_sums[statoff + tx], S);
        atomicAdd(&g_sums[statoff + 32 + tx], Q);
    }
}

// ==================== conv2: cp.async double-buffered, 1 barrier/offset ====
// Input X is pre-activated (BN1+ReLU already applied). Per offset j: issue
// cp.async copies for j+1 into buf^1 (sealed by barrier of j-1), prefetch
// indices for j+2 into registers, compute on buf, cp.wait + barrier.
__global__ void __launch_bounds__(256) conv2a_k(
    const float* __restrict__ X, const float* __restrict__ W,
    const int* __restrict__ rin, const int* __restrict__ rout,
    float* __restrict__ out, int n, int statoff)
{
    const int CIN = 32;
    const int AS = 36;
    const int CSH = 3;

    extern __shared__ float sm[];
    float* C    = sm;                      // 4608
    float* AshB = C + 4608;                // 2 * 4608
    float* WshB = AshB + 9216;             // 2 * 1024
    float* red  = WshB + 2048;             // 512
    int*   dshB = (int*)(red + 512);       // 2 * 128
    int*   klist = dshB + 256;             // 27
    int*   klo   = klist + KOFF;
    int*   kln   = klo + KOFF;
    int*   sst   = kln + KOFF;
    int*   sen   = sst + KOFF;
    int*   nk_sh = sen + KOFF;

    int tx = threadIdx.x;
    int tile = blockIdx.x;
    int r0 = tile * TILE;

    if (tx < KOFF) { sst[tx] = g_seg[tx * SEGW + tile]; sen[tx] = g_seg[tx * SEGW + tile + 1]; }
    for (int i = tx; i < 4608; i += 256) C[i] = 0.f;
    __syncthreads();
    if (tx == 0) {
        int m = 0;
        for (int k = 0; k < KOFF; k++) {
            int L = sen[k] - sst[k];
            if (L > 0) { klist[m] = k; klo[m] = sst[k]; kln[m] = L; m++; }
        }
        *nk_sh = m;
    }
    __syncthreads();
    int nk = *nk_sh;

    // two index-register sets, parity j&1
    int psrc[2][4];
    int pdst[2];

    auto load_idx = [&](int j) {
        int b = j & 1, k = klist[j], s = klo[j], L = kln[j];
        if (tx < L) pdst[b] = __ldg(rout + (size_t)k * n + s + tx);
        #pragma unroll
        for (int i = 0; i < 4; i++) {
            int row = (tx + i * 256) >> CSH;
            if (row < L) psrc[b][i] = __ldg(rin + (size_t)k * n + s + row);
        }
    };

    auto issue_copies = [&](int j) {
        int b = j & 1, k = klist[j], L = kln[j];
        float* Ash = AshB + b * 4608;
        float* Wsh = WshB + b * 1024;
        int*   dsh = dshB + b * 128;
        cp_async16(smem_u32(Wsh + tx * 4), W + (size_t)k * 1024 + tx * 4);
        if (tx < L) dsh[tx] = pdst[b] - r0;
        #pragma unroll
        for (int i = 0; i < 4; i++) {
            int gi = tx + i * 256;
            int row = gi >> CSH, co = gi & 7;
            if (row < L)
                cp_async16(smem_u32(Ash + row * AS + co * 4),
                           X + (size_t)psrc[b][i] * CIN + co * 4);
        }
        CP_COMMIT;
    };

    const int rg = tx >> 3, cg = tx & 7;
    const int rb = rg * 4;

    if (nk > 0) {
        load_idx(0);
        issue_copies(0);
        if (nk > 1) load_idx(1);
        CP_WAIT0;
    }
    __syncthreads();

    for (int j = 0; j < nk; j++) {
        int buf = j & 1;
        int L = kln[j];
        if (j + 1 < nk) issue_copies(j + 1);   // -> buf^1, sealed by barrier j-1
        if (j + 2 < nk) load_idx(j + 2);       // idx set (j+2)&1 == buf (consumed)

        float* Ash = AshB + buf * 4608;
        float* Wsh = WshB + buf * 1024;
        int*   dsh = dshB + buf * 128;

        if (rb < L) {
            float4 cc[4];
            #pragma unroll
            for (int i = 0; i < 4; i++) cc[i] = make_float4(0.f, 0.f, 0.f, 0.f);

            #pragma unroll
            for (int c4 = 0; c4 < CIN / 4; c4++) {
                int ci = c4 * 4;
                float4 a0 = *(const float4*)&Ash[(rb + 0) * AS + ci];
                float4 a1 = *(const float4*)&Ash[(rb + 1) * AS + ci];
                float4 a2 = *(const float4*)&Ash[(rb + 2) * AS + ci];
                float4 a3 = *(const float4*)&Ash[(rb + 3) * AS + ci];
                float4 w0 = *(const float4*)&Wsh[(ci + 0) * 32 + cg * 4];
                float4 w1 = *(const float4*)&Wsh[(ci + 1) * 32 + cg * 4];
                float4 w2 = *(const float4*)&Wsh[(ci + 2) * 32 + cg * 4];
                float4 w3 = *(const float4*)&Wsh[(ci + 3) * 32 + cg * 4];

                cc[0].x = fmaf(a0.x, w0.x, cc[0].x); cc[0].y = fmaf(a0.x, w0.y, cc[0].y);
                cc[0].z = fmaf(a0.x, w0.z, cc[0].z); cc[0].w = fmaf(a0.x, w0.w, cc[0].w);
                cc[1].x = fmaf(a1.x, w0.x, cc[1].x); cc[1].y = fmaf(a1.x, w0.y, cc[1].y);
                cc[1].z = fmaf(a1.x, w0.z, cc[1].z); cc[1].w = fmaf(a1.x, w0.w, cc[1].w);
                cc[2].x = fmaf(a2.x, w0.x, cc[2].x); cc[2].y = fmaf(a2.x, w0.y, cc[2].y);
                cc[2].z = fmaf(a2.x, w0.z, cc[2].z); cc[2].w = fmaf(a2.x, w0.w, cc[2].w);
                cc[3].x = fmaf(a3.x, w0.x, cc[3].x); cc[3].y = fmaf(a3.x, w0.y, cc[3].y);
                cc[3].z = fmaf(a3.x, w0.z, cc[3].z); cc[3].w = fmaf(a3.x, w0.w, cc[3].w);

                cc[0].x = fmaf(a0.y, w1.x, cc[0].x); cc[0].y = fmaf(a0.y, w1.y, cc[0].y);
                cc[0].z = fmaf(a0.y, w1.z, cc[0].z); cc[0].w = fmaf(a0.y, w1.w, cc[0].w);
                cc[1].x = fmaf(a1.y, w1.x, cc[1].x); cc[1].y = fmaf(a1.y, w1.y, cc[1].y);
                cc[1].z = fmaf(a1.y, w1.z, cc[1].z); cc[1].w = fmaf(a1.y, w1.w, cc[1].w);
                cc[2].x = fmaf(a2.y, w1.x, cc[2].x); cc[2].y = fmaf(a2.y, w1.y, cc[2].y);
                cc[2].z = fmaf(a2.y, w1.z, cc[2].z); cc[2].w = fmaf(a2.y, w1.w, cc[2].w);
                cc[3].x = fmaf(a3.y, w1.x, cc[3].x); cc[3].y = fmaf(a3.y, w1.y, cc[3].y);
                cc[3].z = fmaf(a3.y, w1.z, cc[3].z); cc[3].w = fmaf(a3.y, w1.w, cc[3].w);

                cc[0].x = fmaf(a0.z, w2.x, cc[0].x); cc[0].y = fmaf(a0.z, w2.y, cc[0].y);
                cc[0].z = fmaf(a0.z, w2.z, cc[0].z); cc[0].w = fmaf(a0.z, w2.w, cc[0].w);
                cc[1].x = fmaf(a1.z, w2.x, cc[1].x); cc[1].y = fmaf(a1.z, w2.y, cc[1].y);
                cc[1].z = fmaf(a1.z, w2.z, cc[1].z); cc[1].w = fmaf(a1.z, w2.w, cc[1].w);
                cc[2].x = fmaf(a2.z, w2.x, cc[2].x); cc[2].y = fmaf(a2.z, w2.y, cc[2].y);
                cc[2].z = fmaf(a2.z, w2.z, cc[2].z); cc[2].w = fmaf(a2.z, w2.w, cc[2].w);
                cc[3].x = fmaf(a3.z, w2.x, cc[3].x); cc[3].y = fmaf(a3.z, w2.y, cc[3].y);
                cc[3].z = fmaf(a3.z, w2.z, cc[3].z); cc[3].w = fmaf(a3.z, w2.w, cc[3].w);

                cc[0].x = fmaf(a0.w, w3.x, cc[0].x); cc[0].y = fmaf(a0.w, w3.y, cc[0].y);
                cc[0].z = fmaf(a0.w, w3.z, cc[0].z); cc[0].w = fmaf(a0.w, w3.w, cc[0].w);
                cc[1].x = fmaf(a1.w, w3.x, cc[1].x); cc[1].y = fmaf(a1.w, w3.y, cc[1].y);
                cc[1].z = fmaf(a1.w, w3.z, cc[1].z); cc[1].w = fmaf(a1.w, w3.w, cc[1].w);
                cc[2].x = fmaf(a2.w, w3.x, cc[2].x); cc[2].y = fmaf(a2.w, w3.y, cc[2].y);
                cc[2].z = fmaf(a2.w, w3.z, cc[2].z); cc[2].w = fmaf(a2.w, w3.w, cc[2].w);
                cc[3].x = fmaf(a3.w, w3.x, cc[3].x); cc[3].y = fmaf(a3.w, w3.y, cc[3].y);
                cc[3].z = fmaf(a3.w, w3.z, cc[3].z); cc[3].w = fmaf(a3.w, w3.w, cc[3].w);
            }

            #pragma unroll
            for (int i = 0; i < 4; i++) {
                int row = rb + i;
                if (row < L) {
                    float* p = &C[dsh[row] * 36 + cg * 4];   // unique dst: race-free
                    float4 cv = *(float4*)p;
                    cv.x += cc[i].x; cv.y += cc[i].y;
                    cv.z += cc[i].z; cv.w += cc[i].w;
                    *(float4*)p = cv;
                }
            }
        }
        CP_WAIT0;
        __syncthreads();
    }

    int nrows = n - r0; if (nrows > TILE) nrows = TILE;
    for (int i = tx; i < nrows * 8; i += 256) {
        int row = i >> 3, co = i & 7;
        ((float4*)(out + (size_t)(r0 + row) * 32))[co] = *(float4*)&C[row * 36 + co * 4];
    }
    int ch = tx & 31, rb2 = tx >> 5;
    float s = 0.f, q = 0.f;
    for (int r = rb2; r < nrows; r += 8) {
        float v = C[r * 36 + ch];
        s += v;
        q = fmaf(v, v, q);
    }
    red[tx] = s; red[256 + tx] = q;
    __syncthreads();
    if (tx < 32) {
        float S = 0.f, Q = 0.f;
        #pragma unroll
        for (int w = 0; w < 8; w++) { S += red[w * 32 + tx]; Q += red[256 + w * 32 + tx]; }
        atomicAdd(&g_sums[statoff + tx], S);
        atomicAdd(&g_sums[statoff + 32 + tx], Q);
    }
}

// ---------------- BN finalize ----------------------------------------------
__global__ void finalize_k(const float* __restrict__ gamma,
                           const float* __restrict__ beta,
                           int n, int off, int outoff) {
    int c = threadIdx.x;
    float inv_n = 1.f / (float)n;
    float mu  = g_sums[off + c] * inv_n;
    float var = g_sums[off + 32 + c] * inv_n - mu * mu;
    float sc  = gamma[c] * rsqrtf(var + BN_EPS);
    g_sums[outoff + c] = sc;
    g_sums[outoff + 32 + c] = beta[c] - mu * sc;
}

// ---------------- BN apply + ReLU ------------------------------------------
__global__ void apply_k(const float* __restrict__ in, float* __restrict__ out,
                        int n, int soff) {
    int total = n * 8;
    for (int i = blockIdx.x * blockDim.x + threadIdx.x; i < total;
         i += gridDim.x * blockDim.x) {
        int c4 = (i & 7) * 4;
        float4 v  = ((const float4*)in)[i];
        float4 sc = *(const float4*)&g_sums[soff + c4];
        float4 sh = *(const float4*)&g_sums[soff + 32 + c4];
        float4 o;
        o.x = fmaxf(fmaf(v.x, sc.x, sh.x), 0.f);
        o.y = fmaxf(fmaf(v.y, sc.y, sh.y), 0.f);
        o.z = fmaxf(fmaf(v.z, sc.z, sh.z), 0.f);
        o.w = fmaxf(fmaf(v.w, sc.w, sh.w), 0.f);
        ((float4*)out)[i] = o;
    }
}

// ---------------- launch ---------------------------------------------------
static int conv1_smem_bytes() {
    int fl = 128 * 36 + 2 * 128 * 20 + 2 * 16 * 32 + 512 + 64;
    int in = 2 * 128 + KOFF * 5 + 1;
    return (fl + in) * 4 + 16;
}
static int conv2_smem_bytes() {
    int fl = 4608 + 2 * 4608 + 2 * 1024 + 512;
    int in = 2 * 128 + KOFF * 5 + 1;
    return (fl + in) * 4 + 16;
}

extern "C" void kernel_launch(void* const* d_in, const int* in_sizes, int n_in,
                              void* d_out, int out_size) {
    const float* feats  = (const float*)d_in[0];
    const float* W1     = (const float*)d_in[1];
    const float* gamma1 = (const float*)d_in[2];
    const float* beta1  = (const float*)d_in[3];
    const float* W2     = (const float*)d_in[4];
    const float* gamma2 = (const float*)d_in[5];
    const float* beta2  = (const float*)d_in[6];
    const int*   rin    = (const int*)d_in[7];
    const int*   rout   = (const int*)d_in[8];
    int n = in_sizes[0] / 16;

    float *acc1, *x1, *acc2;
    cudaGetSymbolAddress((void**)&acc1, g_acc1);
    cudaGetSymbolAddress((void**)&x1,   g_x1);
    cudaGetSymbolAddress((void**)&acc2, g_acc2);

    int smem1 = conv1_smem_bytes();
    int smem2 = conv2_smem_bytes();
    cudaFuncSetAttribute(conv_k<16, false>, cudaFuncAttributeMaxDynamicSharedMemorySize, smem1);
    cudaFuncSetAttribute(conv2a_k, cudaFuncAttributeMaxDynamicSharedMemorySize, smem2);

    int tiles = (n + TILE - 1) / TILE;
    int segthreads = KOFF * (tiles + 1);

    seg_k<<<(segthreads + 255) / 256, 256>>>(rout, n, tiles);

    conv_k<16, false><<<tiles, 256, smem1>>>(feats, W1, rin, rout, acc1, n, 0);
    finalize_k<<<1, 32>>>(gamma1, beta1, n, 0, 128);
    apply_k<<<1184, 256>>>(acc1, x1, n, 128);

    conv2a_k<<<tiles, 256, smem2>>>(x1, W2, rin, rout, acc2, n, 64);
    finalize_k<<<1, 32>>>(gamma2, beta2, n, 64, 192);

    apply_k<<<1184, 256>>>(acc2, (float*)d_out, n, 192);
}

// round 15
// speedup vs baseline: 1.1003x; 1.1003x over previous
#include <cuda_runtime.h>

#define NMAX 200000
#define KOFF 27
#define TILE 128
#define TILESMAX ((NMAX + TILE - 1) / TILE)
#define SEGW (TILESMAX + 1)
#define BN_EPS 1e-3f

// ---------------- scratch (__device__ globals; no allocs allowed) ----------
__device__ __align__(256) float g_acc1[(size_t)NMAX * 32];
__device__ __align__(256) float g_acc2[(size_t)NMAX * 32];
__device__ int   g_seg[KOFF * SEGW];
// [0:32) L1 sum  [32:64) L1 sumsq  [64:96) L2 sum  [96:128) L2 sumsq
__device__ __align__(16) float g_sums[128];

// ---------------- seg: per (k, dst-tile) pair-range via binary search ------
__global__ void seg_k(const int* __restrict__ rout, int n, int tiles) {
    if (blockIdx.x == 0 && threadIdx.x < 128) g_sums[threadIdx.x] = 0.f;
    int idx = blockIdx.x * blockDim.x + threadIdx.x;
    int total = KOFF * (tiles + 1);
    if (idx >= total) return;
    int k = idx / (tiles + 1), t = idx % (tiles + 1);
    int target = t * TILE;
    if (target > n) target = n;
    const int* a = rout + (size_t)k * n;
    int lo = 0, hi = n;
    while (lo < hi) {
        int mid = (lo + hi) >> 1;
        if (a[mid] < target) lo = mid + 1; else hi = mid;
    }
    g_seg[k * SEGW + t] = lo;
}

// ==================== conv1: pipelined (R4 kernel, verbatim) ===============
template <int CIN>
__global__ void __launch_bounds__(256) conv_k(
    const float* __restrict__ X, const float* __restrict__ W,
    const int* __restrict__ rin, const int* __restrict__ rout,
    float* __restrict__ out, int n, int statoff)
{
    const int AS  = CIN + 4;
    const int CH  = CIN / 4;
    const int CSH = (CIN == 32) ? 3 : 2;
    const int PF  = CH / 2;
    const int WF4 = CIN * 8;

    extern __shared__ float smem[];
    float* C    = smem;                            // 128*36
    float* AshB = C + 128 * 36;                    // 2 * 128*AS
    float* WshB = AshB + 2 * 128 * AS;             // 2 * CIN*32
    float* red  = WshB + 2 * CIN * 32;             // 512
    int*   dshB = (int*)(red + 512);               // 2 * 128
    int*   klist = dshB + 256;
    int*   klo   = klist + KOFF;
    int*   kln   = klo + KOFF;
    int*   sst   = kln + KOFF;
    int*   sen   = sst + KOFF;
    int*   nk_sh = sen + KOFF;

    int tx = threadIdx.x;
    int tile = blockIdx.x;
    int r0 = tile * TILE;

    if (tx < KOFF) { sst[tx] = g_seg[tx * SEGW + tile]; sen[tx] = g_seg[tx * SEGW + tile + 1]; }
    for (int i = tx; i < 128 * 36; i += 256) C[i] = 0.f;
    __syncthreads();
    if (tx == 0) {
        int m = 0;
        for (int k = 0; k < KOFF; k++) {
            int L = sen[k] - sst[k];
            if (L > 0) { klist[m] = k; klo[m] = sst[k]; kln[m] = L; m++; }
        }
        *nk_sh = m;
    }
    __syncthreads();
    int nk = *nk_sh;

    float4 pv[PF];
    float4 pw = make_float4(0.f, 0.f, 0.f, 0.f);
    int pdst = 0;
    int curL = 0;

    auto prefetch = [&](int j) {
        int k = klist[j], s = klo[j], L = kln[j];
        curL = L;
        const float4* Wk4 = (const float4*)(W + (size_t)k * CIN * 32);
        if (tx < WF4) pw = Wk4[tx];
        if (tx < L) pdst = __ldg(rout + (size_t)k * n + s + tx);
        #pragma unroll
        for (int i = 0; i < PF; i++) {
            int gi = tx + i * 256;
            int row = gi >> CSH, co = gi & (CH - 1);
            if (row < L) {
                int src = __ldg(rin + (size_t)k * n + s + row);
                pv[i] = ((const float4*)(X + (size_t)src * CIN))[co];
            }
        }
    };

    if (nk > 0) prefetch(0);

    const int rg = tx >> 3, cg = tx & 7;
    const int rb = rg * 4;

    for (int idx = 0; idx < nk; idx++) {
        int buf = idx & 1;
        int L = curL;
        float* Ash = AshB + buf * 128 * AS;
        float* Wsh = WshB + buf * CIN * 32;
        int*   dsh = dshB + buf * 128;

        if (tx < WF4) ((float4*)Wsh)[tx] = pw;
        if (tx < L) dsh[tx] = pdst - r0;
        #pragma unroll
        for (int i = 0; i < PF; i++) {
            int gi = tx + i * 256;
            int row = gi >> CSH, co = gi & (CH - 1);
            if (row < L) *(float4*)&Ash[row * AS + co * 4] = pv[i];
        }
        __syncthreads();

        if (idx + 1 < nk) prefetch(idx + 1);

        if (rb < L) {
            float4 cc[4];
            #pragma unroll
            for (int i = 0; i < 4; i++) cc[i] = make_float4(0.f, 0.f, 0.f, 0.f);

            #pragma unroll
            for (int c4 = 0; c4 < CIN / 4; c4++) {
                int ci = c4 * 4;
                float4 a0 = *(const float4*)&Ash[(rb + 0) * AS + ci];
                float4 a1 = *(const float4*)&Ash[(rb + 1) * AS + ci];
                float4 a2 = *(const float4*)&Ash[(rb + 2) * AS + ci];
                float4 a3 = *(const float4*)&Ash[(rb + 3) * AS + ci];
                float4 w0 = *(const float4*)&Wsh[(ci + 0) * 32 + cg * 4];
                float4 w1 = *(const float4*)&Wsh[(ci + 1) * 32 + cg * 4];
                float4 w2 = *(const float4*)&Wsh[(ci + 2) * 32 + cg * 4];
                float4 w3 = *(const float4*)&Wsh[(ci + 3) * 32 + cg * 4];

                cc[0].x = fmaf(a0.x, w0.x, cc[0].x); cc[0].y = fmaf(a0.x, w0.y, cc[0].y);
                cc[0].z = fmaf(a0.x, w0.z, cc[0].z); cc[0].w = fmaf(a0.x, w0.w, cc[0].w);
                cc[1].x = fmaf(a1.x, w0.x, cc[1].x); cc[1].y = fmaf(a1.x, w0.y, cc[1].y);
                cc[1].z = fmaf(a1.x, w0.z, cc[1].z); cc[1].w = fmaf(a1.x, w0.w, cc[1].w);
                cc[2].x = fmaf(a2.x, w0.x, cc[2].x); cc[2].y = fmaf(a2.x, w0.y, cc[2].y);
                cc[2].z = fmaf(a2.x, w0.z, cc[2].z); cc[2].w = fmaf(a2.x, w0.w, cc[2].w);
                cc[3].x = fmaf(a3.x, w0.x, cc[3].x); cc[3].y = fmaf(a3.x, w0.y, cc[3].y);
                cc[3].z = fmaf(a3.x, w0.z, cc[3].z); cc[3].w = fmaf(a3.x, w0.w, cc[3].w);

                cc[0].x = fmaf(a0.y, w1.x, cc[0].x); cc[0].y = fmaf(a0.y, w1.y, cc[0].y);
                cc[0].z = fmaf(a0.y, w1.z, cc[0].z); cc[0].w = fmaf(a0.y, w1.w, cc[0].w);
                cc[1].x = fmaf(a1.y, w1.x, cc[1].x); cc[1].y = fmaf(a1.y, w1.y, cc[1].y);
                cc[1].z = fmaf(a1.y, w1.z, cc[1].z); cc[1].w = fmaf(a1.y, w1.w, cc[1].w);
                cc[2].x = fmaf(a2.y, w1.x, cc[2].x); cc[2].y = fmaf(a2.y, w1.y, cc[2].y);
                cc[2].z = fmaf(a2.y, w1.z, cc[2].z); cc[2].w = fmaf(a2.y, w1.w, cc[2].w);
                cc[3].x = fmaf(a3.y, w1.x, cc[3].x); cc[3].y = fmaf(a3.y, w1.y, cc[3].y);
                cc[3].z = fmaf(a3.y, w1.z, cc[3].z); cc[3].w = fmaf(a3.y, w1.w, cc[3].w);

                cc[0].x = fmaf(a0.z, w2.x, cc[0].x); cc[0].y = fmaf(a0.z, w2.y, cc[0].y);
                cc[0].z = fmaf(a0.z, w2.z, cc[0].z); cc[0].w = fmaf(a0.z, w2.w, cc[0].w);
                cc[1].x = fmaf(a1.z, w2.x, cc[1].x); cc[1].y = fmaf(a1.z, w2.y, cc[1].y);
                cc[1].z = fmaf(a1.z, w2.z, cc[1].z); cc[1].w = fmaf(a1.z, w2.w, cc[1].w);
                cc[2].x = fmaf(a2.z, w2.x, cc[2].x); cc[2].y = fmaf(a2.z, w2.y, cc[2].y);
                cc[2].z = fmaf(a2.z, w2.z, cc[2].z); cc[2].w = fmaf(a2.z, w2.w, cc[2].w);
                cc[3].x = fmaf(a3.z, w2.x, cc[3].x); cc[3].y = fmaf(a3.z, w2.y, cc[3].y);
                cc[3].z = fmaf(a3.z, w2.z, cc[3].z); cc[3].w = fmaf(a3.z, w2.w, cc[3].w);

                cc[0].x = fmaf(a0.w, w3.x, cc[0].x); cc[0].y = fmaf(a0.w, w3.y, cc[0].y);
                cc[0].z = fmaf(a0.w, w3.z, cc[0].z); cc[0].w = fmaf(a0.w, w3.w, cc[0].w);
                cc[1].x = fmaf(a1.w, w3.x, cc[1].x); cc[1].y = fmaf(a1.w, w3.y, cc[1].y);
                cc[1].z = fmaf(a1.w, w3.z, cc[1].z); cc[1].w = fmaf(a1.w, w3.w, cc[1].w);
                cc[2].x = fmaf(a2.w, w3.x, cc[2].x); cc[2].y = fmaf(a2.w, w3.y, cc[2].y);
                cc[2].z = fmaf(a2.w, w3.z, cc[2].z); cc[2].w = fmaf(a2.w, w3.w, cc[2].w);
                cc[3].x = fmaf(a3.w, w3.x, cc[3].x); cc[3].y = fmaf(a3.w, w3.y, cc[3].y);
                cc[3].z = fmaf(a3.w, w3.z, cc[3].z); cc[3].w = fmaf(a3.w, w3.w, cc[3].w);
            }

            #pragma unroll
            for (int i = 0; i < 4; i++) {
                int row = rb + i;
                if (row < L) {
                    float* p = &C[dsh[row] * 36 + cg * 4];
                    float4 cv = *(float4*)p;
                    cv.x += cc[i].x; cv.y += cc[i].y;
                    cv.z += cc[i].z; cv.w += cc[i].w;
                    *(float4*)p = cv;
                }
            }
        }
    }
    __syncthreads();

    int nrows = n - r0; if (nrows > 128) nrows = 128;
    for (int i = tx; i < nrows * 8; i += 256) {
        int row = i >> 3, co = i & 7;
        ((float4*)(out + (size_t)(r0 + row) * 32))[co] = *(float4*)&C[row * 36 + co * 4];
    }
    int ch = tx & 31, rb2 = tx >> 5;
    float s = 0.f, q = 0.f;
    for (int r = rb2; r < nrows; r += 8) {
        float v = C[r * 36 + ch];
        s += v;
        q = fmaf(v, v, q);
    }
    red[tx] = s; red[256 + tx] = q;
    __syncthreads();
    if (tx < 32) {
        float S = 0.f, Q = 0.f;
        #pragma unroll
        for (int w = 0; w < 8; w++) { S += red[w * 32 + tx]; Q += red[256 + w * 32 + tx]; }
        atomicAdd(&g_sums[statoff + tx], S);
        atomicAdd(&g_sums[statoff + 32 + tx], Q);
    }
}

// ==================== conv2: R13 kernel + fused BN1 finalize ===============
// Identical to R13's conv2s_k (213.6us) except each block computes the BN1
// scale/shift locally from g_sums sums + gamma1/beta1 (removes a launch).
__global__ void __launch_bounds__(256) conv2s_k(
    const float* __restrict__ X, const float* __restrict__ W,
    const int* __restrict__ rin, const int* __restrict__ rout,
    float* __restrict__ out, int n,
    const float* __restrict__ gamma1, const float* __restrict__ beta1)
{
    const int CIN = 32;
    const int AS = CIN + 4;               // 36
    const int CH = CIN / 4;               // 8
    const int CSH = 3;
    __shared__ __align__(16) float C[128 * 36];
    __shared__ __align__(16) float Ash[128 * 36];
    __shared__ __align__(16) float Wsh[CIN * 32];
    __shared__ __align__(16) float red[512];
    __shared__ __align__(16) float bns[64];
    __shared__ __align__(16) int   dsh[128];
    __shared__ __align__(16) int   klist[28], klo[28], kln[28];
    __shared__ __align__(16) int   sst[28], sen[28];
    __shared__ int nk_sh;

    int tx = threadIdx.x;
    int tile = blockIdx.x;
    int r0 = tile * TILE;

    // fused BN1 finalize: per-block scale/shift from global sums
    if (tx < 32) {
        float inv_n = 1.f / (float)n;
        float mu  = g_sums[tx] * inv_n;
        float var = g_sums[32 + tx] * inv_n - mu * mu;
        float sc  = gamma1[tx] * rsqrtf(var + BN_EPS);
        bns[tx] = sc;
        bns[32 + tx] = beta1[tx] - mu * sc;
    }
    if (tx < KOFF) { sst[tx] = g_seg[tx * SEGW + tile]; sen[tx] = g_seg[tx * SEGW + tile + 1]; }
    for (int i = tx; i < 128 * 36; i += 256) C[i] = 0.f;
    __syncthreads();
    if (tx == 0) {
        int m = 0;
        for (int k = 0; k < KOFF; k++) {
            int L = sen[k] - sst[k];
            if (L > 0) { klist[m] = k; klo[m] = sst[k]; kln[m] = L; m++; }
        }
        nk_sh = m;
    }
    __syncthreads();
    int nk = nk_sh;

    const int rg = tx >> 3, cg = tx & 7;
    const int rb = rg * 4;

    int psrc[4];
    int pdst = 0;

    auto pref_idx = [&](int j) {
        int k = klist[j], s = klo[j], L = kln[j];
        if (tx < L) pdst = __ldg(rout + (size_t)k * n + s + tx);
        #pragma unroll
        for (int i = 0; i < 4; i++) {
            int row = (tx + i * 256) >> CSH;
            if (row < L) psrc[i] = __ldg(rin + (size_t)k * n + s + row);
        }
    };

    if (nk > 0) pref_idx(0);

    for (int j = 0; j < nk; j++) {
        int k = klist[j], L = kln[j];
        __syncthreads();                  // prev compute done before restage

        const float4* Wk4 = (const float4*)(W + (size_t)k * CIN * 32);
        if (tx < CIN * 8) ((float4*)Wsh)[tx] = Wk4[tx];

        if (tx < L) dsh[tx] = pdst - r0;
        #pragma unroll
        for (int i = 0; i < 4; i++) {
            int gi = tx + i * 256;
            int row = gi >> CSH, co = gi & (CH - 1);
            if (row < L) {
                float4 v = ((const float4*)(X + (size_t)psrc[i] * CIN))[co];
                float4 sc = *(const float4*)&bns[co * 4];
                float4 sh = *(const float4*)&bns[32 + co * 4];
                v.x = fmaxf(fmaf(v.x, sc.x, sh.x), 0.f);
                v.y = fmaxf(fmaf(v.y, sc.y, sh.y), 0.f);
                v.z = fmaxf(fmaf(v.z, sc.z, sh.z), 0.f);
                v.w = fmaxf(fmaf(v.w, sc.w, sh.w), 0.f);
                *(float4*)&Ash[row * AS + co * 4] = v;
            }
        }
        __syncthreads();

        if (j + 1 < nk) pref_idx(j + 1);  // hidden under compute below

        if (rb < L) {
            float4 cc[4];
            #pragma unroll
            for (int i = 0; i < 4; i++) cc[i] = make_float4(0.f, 0.f, 0.f, 0.f);

            #pragma unroll
            for (int c4 = 0; c4 < CIN / 4; c4++) {
                int ci = c4 * 4;
                float4 a0 = *(const float4*)&Ash[(rb + 0) * AS + ci];
                float4 a1 = *(const float4*)&Ash[(rb + 1) * AS + ci];
                float4 a2 = *(const float4*)&Ash[(rb + 2) * AS + ci];
                float4 a3 = *(const float4*)&Ash[(rb + 3) * AS + ci];
                float4 w0 = *(const float4*)&Wsh[(ci + 0) * 32 + cg * 4];
                float4 w1 = *(const float4*)&Wsh[(ci + 1) * 32 + cg * 4];
                float4 w2 = *(const float4*)&Wsh[(ci + 2) * 32 + cg * 4];
                float4 w3 = *(const float4*)&Wsh[(ci + 3) * 32 + cg * 4];

                cc[0].x = fmaf(a0.x, w0.x, cc[0].x); cc[0].y = fmaf(a0.x, w0.y, cc[0].y);
                cc[0].z = fmaf(a0.x, w0.z, cc[0].z); cc[0].w = fmaf(a0.x, w0.w, cc[0].w);
                cc[1].x = fmaf(a1.x, w0.x, cc[1].x); cc[1].y = fmaf(a1.x, w0.y, cc[1].y);
                cc[1].z = fmaf(a1.x, w0.z, cc[1].z); cc[1].w = fmaf(a1.x, w0.w, cc[1].w);
                cc[2].x = fmaf(a2.x, w0.x, cc[2].x); cc[2].y = fmaf(a2.x, w0.y, cc[2].y);
                cc[2].z = fmaf(a2.x, w0.z, cc[2].z); cc[2].w = fmaf(a2.x, w0.w, cc[2].w);
                cc[3].x = fmaf(a3.x, w0.x, cc[3].x); cc[3].y = fmaf(a3.x, w0.y, cc[3].y);
                cc[3].z = fmaf(a3.x, w0.z, cc[3].z); cc[3].w = fmaf(a3.x, w0.w, cc[3].w);

                cc[0].x = fmaf(a0.y, w1.x, cc[0].x); cc[0].y = fmaf(a0.y, w1.y, cc[0].y);
                cc[0].z = fmaf(a0.y, w1.z, cc[0].z); cc[0].w = fmaf(a0.y, w1.w, cc[0].w);
                cc[1].x = fmaf(a1.y, w1.x, cc[1].x); cc[1].y = fmaf(a1.y, w1.y, cc[1].y);
                cc[1].z = fmaf(a1.y, w1.z, cc[1].z); cc[1].w = fmaf(a1.y, w1.w, cc[1].w);
                cc[2].x = fmaf(a2.y, w1.x, cc[2].x); cc[2].y = fmaf(a2.y, w1.y, cc[2].y);
                cc[2].z = fmaf(a2.y, w1.z, cc[2].z); cc[2].w = fmaf(a2.y, w1.w, cc[2].w);
                cc[3].x = fmaf(a3.y, w1.x, cc[3].x); cc[3].y = fmaf(a3.y, w1.y, cc[3].y);
                cc[3].z = fmaf(a3.y, w1.z, cc[3].z); cc[3].w = fmaf(a3.y, w1.w, cc[3].w);

                cc[0].x = fmaf(a0.z, w2.x, cc[0].x); cc[0].y = fmaf(a0.z, w2.y, cc[0].y);
                cc[0].z = fmaf(a0.z, w2.z, cc[0].z); cc[0].w = fmaf(a0.z, w2.w, cc[0].w);
                cc[1].x = fmaf(a1.z, w2.x, cc[1].x); cc[1].y = fmaf(a1.z, w2.y, cc[1].y);
                cc[1].z = fmaf(a1.z, w2.z, cc[1].z); cc[1].w = fmaf(a1.z, w2.w, cc[1].w);
                cc[2].x = fmaf(a2.z, w2.x, cc[2].x); cc[2].y = fmaf(a2.z, w2.y, cc[2].y);
                cc[2].z = fmaf(a2.z, w2.z, cc[2].z); cc[2].w = fmaf(a2.z, w2.w, cc[2].w);
                cc[3].x = fmaf(a3.z, w2.x, cc[3].x); cc[3].y = fmaf(a3.z, w2.y, cc[3].y);
                cc[3].z = fmaf(a3.z, w2.z, cc[3].z); cc[3].w = fmaf(a3.z, w2.w, cc[3].w);

                cc[0].x = fmaf(a0.w, w3.x, cc[0].x); cc[0].y = fmaf(a0.w, w3.y, cc[0].y);
                cc[0].z = fmaf(a0.w, w3.z, cc[0].z); cc[0].w = fmaf(a0.w, w3.w, cc[0].w);
                cc[1].x = fmaf(a1.w, w3.x, cc[1].x); cc[1].y = fmaf(a1.w, w3.y, cc[1].y);
                cc[1].z = fmaf(a1.w, w3.z, cc[1].z); cc[1].w = fmaf(a1.w, w3.w, cc[1].w);
                cc[2].x = fmaf(a2.w, w3.x, cc[2].x); cc[2].y = fmaf(a2.w, w3.y, cc[2].y);
                cc[2].z = fmaf(a2.w, w3.z, cc[2].z); cc[2].w = fmaf(a2.w, w3.w, cc[2].w);
                cc[3].x = fmaf(a3.w, w3.x, cc[3].x); cc[3].y = fmaf(a3.w, w3.y, cc[3].y);
                cc[3].z = fmaf(a3.w, w3.z, cc[3].z); cc[3].w = fmaf(a3.w, w3.w, cc[3].w);
            }

            #pragma unroll
            for (int i = 0; i < 4; i++) {
                int row = rb + i;
                if (row < L) {
                    float* p = &C[dsh[row] * 36 + cg * 4];   // unique dst: race-free
                    float4 cv = *(float4*)p;
                    cv.x += cc[i].x; cv.y += cc[i].y;
                    cv.z += cc[i].z; cv.w += cc[i].w;
                    *(float4*)p = cv;
                }
            }
        }
    }
    __syncthreads();

    int nrows = n - r0; if (nrows > 128) nrows = 128;
    for (int i = tx; i < nrows * 8; i += 256) {
        int row = i >> 3, co = i & 7;
        ((float4*)(out + (size_t)(r0 + row) * 32))[co] = *(float4*)&C[row * 36 + co * 4];
    }
    int ch = tx & 31, rb2 = tx >> 5;
    float s = 0.f, q = 0.f;
    for (int r = rb2; r < nrows; r += 8) {
        float v = C[r * 36 + ch];
        s += v;
        q = fmaf(v, v, q);
    }
    red[tx] = s; red[256 + tx] = q;
    __syncthreads();
    if (tx < 32) {
        float S = 0.f, Q = 0.f;
        #pragma unroll
        for (int w = 0; w < 8; w++) { S += red[w * 32 + tx]; Q += red[256 + w * 32 + tx]; }
        atomicAdd(&g_sums[64 + tx], S);
        atomicAdd(&g_sums[96 + tx], Q);
    }
}

// ---------------- BN2 apply + ReLU with fused finalize ---------------------
__global__ void apply2_k(const float* __restrict__ in, float* __restrict__ out,
                         int n, const float* __restrict__ gamma,
                         const float* __restrict__ beta) {
    __shared__ __align__(16) float scs[32];
    __shared__ __align__(16) float shs[32];
    if (threadIdx.x < 32) {
        int c = threadIdx.x;
        float inv_n = 1.f / (float)n;
        float mu  = g_sums[64 + c] * inv_n;
        float var = g_sums[96 + c] * inv_n - mu * mu;
        float sc  = gamma[c] * rsqrtf(var + BN_EPS);
        scs[c] = sc;
        shs[c] = beta[c] - mu * sc;
    }
    __syncthreads();
    int total = n * 8;
    for (int i = blockIdx.x * blockDim.x + threadIdx.x; i < total;
         i += gridDim.x * blockDim.x) {
        int c4 = (i & 7) * 4;
        float4 v  = ((const float4*)in)[i];
        float4 sc = *(const float4*)&scs[c4];
        float4 sh = *(const float4*)&shs[c4];
        float4 o;
        o.x = fmaxf(fmaf(v.x, sc.x, sh.x), 0.f);
        o.y = fmaxf(fmaf(v.y, sc.y, sh.y), 0.f);
        o.z = fmaxf(fmaf(v.z, sc.z, sh.z), 0.f);
        o.w = fmaxf(fmaf(v.w, sc.w, sh.w), 0.f);
        ((float4*)out)[i] = o;
    }
}

// ---------------- launch ---------------------------------------------------
static int conv1_smem_bytes() {
    int fl = 128 * 36 + 2 * 128 * 20 + 2 * 16 * 32 + 512;
    int in = 2 * 128 + KOFF * 5 + 1;
    return (fl + in) * 4 + 16;
}

extern "C" void kernel_launch(void* const* d_in, const int* in_sizes, int n_in,
                              void* d_out, int out_size) {
    const float* feats  = (const float*)d_in[0];
    const float* W1     = (const float*)d_in[1];
    const float* gamma1 = (const float*)d_in[2];
    const float* beta1  = (const float*)d_in[3];
    const float* W2     = (const float*)d_in[4];
    const float* gamma2 = (const float*)d_in[5];
    const float* beta2  = (const float*)d_in[6];
    const int*   rin    = (const int*)d_in[7];
    const int*   rout   = (const int*)d_in[8];
    int n = in_sizes[0] / 16;

    float *acc1, *acc2;
    cudaGetSymbolAddress((void**)&acc1, g_acc1);
    cudaGetSymbolAddress((void**)&acc2, g_acc2);

    int smem1 = conv1_smem_bytes();
    cudaFuncSetAttribute(conv_k<16>, cudaFuncAttributeMaxDynamicSharedMemorySize, smem1);

    int tiles = (n + TILE - 1) / TILE;
    int segthreads = KOFF * (tiles + 1);

    seg_k<<<(segthreads + 255) / 256, 256>>>(rout, n, tiles);

    conv_k<16><<<tiles, 256, smem1>>>(feats, W1, rin, rout, acc1, n, 0);

    conv2s_k<<<tiles, 256>>>(acc1, W2, rin, rout, acc2, n, gamma1, beta1);

    apply2_k<<<1184, 256>>>(acc2, (float*)d_out, n, gamma2, beta2);
}